// round 6
// baseline (speedup 1.0000x reference)
#include <cuda_runtime.h>
#include <cstdint>
#include <cstddef>

// ---------------------------------------------------------------------------
// Critic_Mix fused kernel (round 5): mma.sync tf32 + ldmatrix.x4 + cp.async
// weight images. R5: split-K across warp pairs (512 threads, 16 warps/SM),
// SMEM pair-reduction in the dead weight buffer. Traffic ~unchanged, 2x warps.
// ---------------------------------------------------------------------------

#define THREADS   512
#define BM        64
#define BATCH     262144
#define NBLK      (BATCH / BM)

#define ACT_B      32768
#define WBUF_OFF   (5 * ACT_B)          // 163840
#define BIAS_OFF   (WBUF_OFF + 65536)   // 229376
#define SMEM_BYTES (BIAS_OFF + 1024)    // 230400 <= 232448
#define BIAS_F     (BIAS_OFF / 4)

#define SWF(row, k) (((row) * 128) + ((k) ^ (((row) & 7) << 2)))

__device__ float g_wimg[30 * 16384];
__device__ float g_bimg[30 * 128];

struct Params {
    const float* x;
    const float* u;
    const float* mixf;
    const float* P;
    const float* W[2][3];
    const float* Bb[2][3];
    const float* W4[2];
    const float* b4[2];
    const float* tW[2][3];
    const float* tb[2][3];
    float*       out;
};

__device__ __forceinline__ float to_tf32(float x) {
    asm("cvt.rna.tf32.f32 %0, %0;" : "+f"(x));
    return x;
}
__device__ __forceinline__ uint32_t s2u(const void* p) {
    uint32_t a;
    asm("{ .reg .u64 t; cvta.to.shared.u64 t, %1; cvt.u32.u64 %0, t; }"
        : "=r"(a) : "l"(p));
    return a;
}
__device__ __forceinline__ void ldsm4(uint32_t* r, uint32_t addr) {
    asm volatile("ldmatrix.sync.aligned.m8n8.x4.shared.b16 {%0,%1,%2,%3}, [%4];"
                 : "=r"(r[0]), "=r"(r[1]), "=r"(r[2]), "=r"(r[3]) : "r"(addr));
}
__device__ __forceinline__ void mma8(float* c, const uint32_t* a,
                                     uint32_t b0, uint32_t b1) {
    asm volatile(
        "mma.sync.aligned.m16n8k8.row.col.f32.tf32.tf32.f32 "
        "{%0,%1,%2,%3}, {%4,%5,%6,%7}, {%8,%9}, {%0,%1,%2,%3};"
        : "+f"(c[0]), "+f"(c[1]), "+f"(c[2]), "+f"(c[3])
        : "r"(a[0]), "r"(a[1]), "r"(a[2]), "r"(a[3]), "r"(b0), "r"(b1));
}
__device__ __forceinline__ void cpasync16(uint32_t dst, const void* src) {
    asm volatile("cp.async.cg.shared.global [%0], [%1], 16;"
                 :: "r"(dst), "l"(src) : "memory");
}

// ---------------- preprocessing kernel ----------------
__global__ void prep_kernel(Params p) {
    const int idx = blockIdx.x * 256 + threadIdx.x;
    if (idx < 30 * 4096) {
        const int img = idx >> 12;
        const int rem = idx & 4095;
        const int n   = rem >> 5;
        const int q   = rem & 31;
        const int h = img / 15, rr = img % 15, L = rr / 5, s = rr % 5;
        const int O = (L == 2) ? 64 : 128;
        float4 v = make_float4(0.f, 0.f, 0.f, 0.f);
        if (n < O) {
            const float* W = (s == 4) ? p.W[h][L]
                                      : p.tW[h][L] + (size_t)s * O * 128;
            v = *reinterpret_cast<const float4*>(W + (size_t)n * 128 + q * 4);
            v.x = to_tf32(v.x); v.y = to_tf32(v.y);
            v.z = to_tf32(v.z); v.w = to_tf32(v.w);
        }
        const int off = SWF(n, q * 4);
        *reinterpret_cast<float4*>(g_wimg + (size_t)img * 16384 + off) = v;
    } else if (idx < 30 * 4096 + 960) {
        const int b   = idx - 30 * 4096;
        const int img = b >> 5;
        const int q   = b & 31;
        const int h = img / 15, rr = img % 15, L = rr / 5, s = rr % 5;
        const int O = (L == 2) ? 64 : 128;
        const float* B = (s == 4) ? p.Bb[h][L] : p.tb[h][L] + s * O;
        const int o = q * 4;
        float4 v;
        v.x = (o + 0 < O) ? B[o + 0] : 0.f;
        v.y = (o + 1 < O) ? B[o + 1] : 0.f;
        v.z = (o + 2 < O) ? B[o + 2] : 0.f;
        v.w = (o + 3 < O) ? B[o + 3] : 0.f;
        *reinterpret_cast<float4*>(g_bimg + img * 128 + o) = v;
    }
}

// ---------------- main kernel ----------------
// nv: number of 8KB chunks to fetch (8 full, 4 for L=2 half images)
__device__ __forceinline__ void prefetch_img(uint32_t wbuf_u, uint32_t bias_u,
                                             int img, int slot, int nv, int tid) {
    const float4* wsrc = reinterpret_cast<const float4*>(g_wimg + (size_t)img * 16384);
    #pragma unroll
    for (int i = 0; i < 8; i++)
        if (i < nv)
            cpasync16(wbuf_u + (uint32_t)(tid + i * 512) * 16, wsrc + tid + i * 512);
    if (tid < 32)
        cpasync16(bias_u + (uint32_t)slot * 512 + tid * 16,
                  reinterpret_cast<const float4*>(g_bimg + img * 128) + tid);
    asm volatile("cp.async.commit_group;" ::: "memory");
}

__global__ void __launch_bounds__(THREADS, 1)
critic_main(Params p) {
    extern __shared__ float smem[];
    const uint32_t sbase  = s2u(smem);
    const uint32_t wbuf_u = sbase + WBUF_OFF;
    const uint32_t bias_u = sbase + BIAS_OFF;

    const int tid  = threadIdx.x;
    const int lane = tid & 31;
    const int wid  = tid >> 5;            // 0..15
    const int kk   = wid & 1;             // k-half
    const int wm   = (wid >> 1) & 1;      // batch half
    const int wn   = wid >> 2;            // output quarter (0..3)
    const int pairId = wid >> 1;          // 0..7, shared by kk pair
    const int mbase = wm * 32;
    const int nbase = wn * 32;
    const int lq = lane >> 2, lr = lane & 3;
    const int r8 = lane & 7, sel = lane >> 3;
    const int row0 = blockIdx.x * BM;
    const bool lowN = (wn < 2);

    const int rowA0 = mbase + ((sel & 1) << 3) + r8;
    const int rowA1 = rowA0 + 16;
    const int rowB0 = nbase + ((sel >> 1) << 3) + r8;
    const int rowB1 = rowB0 + 16;
    const uint32_t mA = ((((sel >> 1) << 2) ^ (r8 << 2)) << 2);
    const uint32_t mB = ((((sel & 1) << 2) ^ (r8 << 2)) << 2);
    const uint32_t aoff0 = (uint32_t)rowA0 * 512;
    const uint32_t aoff1 = (uint32_t)rowA1 * 512;
    const uint32_t boff0 = wbuf_u + (uint32_t)rowB0 * 512;
    const uint32_t boff1 = wbuf_u + (uint32_t)rowB1 * 512;
    const uint32_t kbase = (uint32_t)(kk * 8 * 32);   // byte offset of k-half

    // reduction slot (in dead wbuf): pair-contiguous, lane-contiguous 16B
    const uint32_t red_u = wbuf_u + (uint32_t)pairId * 4096 + (uint32_t)lane * 16;

    const float m = __ldg(p.mixf);
    const float inv_m = 1.0f - m;
    float Pk[4];
    #pragma unroll
    for (int k = 0; k < 4; k++) Pk[k] = __ldg(p.P + k);

    for (int h = 0; h < 2; h++) {
        prefetch_img(wbuf_u, bias_u, h * 15, 0, 8, tid);

        // ---- xu -> act buffer 4 ----
        {
            float* dst = smem + 4 * (ACT_B / 4);
            #pragma unroll
            for (int i = tid; i < 64 * 32; i += THREADS) {
                const int r = i >> 5;
                const int q = i & 31;
                float4 v;
                if (q < 24)
                    v = *reinterpret_cast<const float4*>(
                        p.x + (size_t)(row0 + r) * 96 + q * 4);
                else
                    v = *reinterpret_cast<const float4*>(
                        p.u + (size_t)(row0 + r) * 32 + (q - 24) * 4);
                v.x = to_tf32(v.x); v.y = to_tf32(v.y);
                v.z = to_tf32(v.z); v.w = to_tf32(v.w);
                *reinterpret_cast<float4*>(dst + SWF(r, q * 4)) = v;
            }
        }

        float mix[2][4][4];
        for (int t = 0; t < 15; t++) {
            const int L = t / 5, s = t % 5;
            const bool is_main = (s == 4);
            const bool active  = (L < 2) || lowN;
            if (s == 0) {
                #pragma unroll
                for (int mt = 0; mt < 2; mt++)
                    #pragma unroll
                    for (int nt = 0; nt < 4; nt++)
                        #pragma unroll
                        for (int c = 0; c < 4; c++) mix[mt][nt][c] = 0.f;
            }

            asm volatile("cp.async.wait_group 0;" ::: "memory");
            __syncthreads();

            float acc[2][4][4];
            #pragma unroll
            for (int mt = 0; mt < 2; mt++)
                #pragma unroll
                for (int nt = 0; nt < 4; nt++)
                    #pragma unroll
                    for (int c = 0; c < 4; c++) acc[mt][nt][c] = 0.f;

            if (active) {
                const int inb = (L == 0) ? 4 : (is_main ? 4 : s);
                const uint32_t abase0 = sbase + (uint32_t)inb * ACT_B + aoff0;
                const uint32_t abase1 = sbase + (uint32_t)inb * ACT_B + aoff1;

                uint32_t fa0[2][4], fa1[2][4], fb0[2][4], fb1[2][4];
                {
                    const uint32_t offA = kbase ^ mA, offB = kbase ^ mB;
                    ldsm4(fa0[0], abase0 + offA);
                    ldsm4(fa1[0], abase1 + offA);
                    ldsm4(fb0[0], boff0 + offB);
                    ldsm4(fb1[0], boff1 + offB);
                }
                #pragma unroll
                for (int jj = 0; jj < 8; jj++) {
                    const int cur = jj & 1, nxt = cur ^ 1;
                    if (jj < 7) {
                        const uint32_t kb = kbase + (uint32_t)((jj + 1) * 32);
                        const uint32_t offA = kb ^ mA, offB = kb ^ mB;
                        ldsm4(fa0[nxt], abase0 + offA);
                        ldsm4(fa1[nxt], abase1 + offA);
                        ldsm4(fb0[nxt], boff0 + offB);
                        ldsm4(fb1[nxt], boff1 + offB);
                    }
                    mma8(acc[0][0], fa0[cur], fb0[cur][0], fb0[cur][1]);
                    mma8(acc[0][1], fa0[cur], fb0[cur][2], fb0[cur][3]);
                    mma8(acc[0][2], fa0[cur], fb1[cur][0], fb1[cur][1]);
                    mma8(acc[0][3], fa0[cur], fb1[cur][2], fb1[cur][3]);
                    mma8(acc[1][0], fa1[cur], fb0[cur][0], fb0[cur][1]);
                    mma8(acc[1][1], fa1[cur], fb0[cur][2], fb0[cur][3]);
                    mma8(acc[1][2], fa1[cur], fb1[cur][0], fb1[cur][1]);
                    mma8(acc[1][3], fa1[cur], fb1[cur][2], fb1[cur][3]);
                }
            }

            __syncthreads();    // k-loop reads of wbuf/act done

            // ---- split-K pair reduction through (dead) wbuf ----
            if (active && kk == 1) {
                #pragma unroll
                for (int mt = 0; mt < 2; mt++)
                    #pragma unroll
                    for (int nt = 0; nt < 4; nt++) {
                        const int i = mt * 4 + nt;
                        float4 v = make_float4(acc[mt][nt][0], acc[mt][nt][1],
                                               acc[mt][nt][2], acc[mt][nt][3]);
                        *reinterpret_cast<float4*>(
                            (char*)smem + (red_u - sbase) + i * 512) = v;
                    }
            }
            __syncthreads();
            if (active && kk == 0) {
                #pragma unroll
                for (int mt = 0; mt < 2; mt++)
                    #pragma unroll
                    for (int nt = 0; nt < 4; nt++) {
                        const int i = mt * 4 + nt;
                        const float4 v = *reinterpret_cast<const float4*>(
                            (char*)smem + (red_u - sbase) + i * 512);
                        acc[mt][nt][0] += v.x; acc[mt][nt][1] += v.y;
                        acc[mt][nt][2] += v.z; acc[mt][nt][3] += v.w;
                    }
            }
            __syncthreads();    // reduction reads done -> wbuf reusable

            if (t < 14) {
                const int nL = (t + 1) / 5;
                prefetch_img(wbuf_u, bias_u, h * 15 + t + 1, (t + 1) & 1,
                             (nL == 2) ? 4 : 8, tid);
            }

            if (active && kk == 0) {
                const float sc = is_main ? inv_m : (m * Pk[s]);
                const int bslot = BIAS_F + (t & 1) * 128;
                float bias[4][2];
                #pragma unroll
                for (int nt = 0; nt < 4; nt++) {
                    bias[nt][0] = smem[bslot + nbase + nt * 8 + lr * 2 + 0];
                    bias[nt][1] = smem[bslot + nbase + nt * 8 + lr * 2 + 1];
                }
                const bool do_store = is_main || (L < 2);
                float* outb = smem + (is_main ? 4 : s) * (ACT_B / 4);
                #pragma unroll
                for (int mt = 0; mt < 2; mt++)
                    #pragma unroll
                    for (int nt = 0; nt < 4; nt++)
                        #pragma unroll
                        for (int c = 0; c < 4; c++) {
                            const float val = acc[mt][nt][c] + bias[nt][c & 1];
                            float ov;
                            if (!is_main) {
                                mix[mt][nt][c] = fmaf(sc, val, mix[mt][nt][c]);
                                ov = val;
                            } else {
                                ov = fmaf(sc, val, mix[mt][nt][c]);
                            }
                            if (do_store) {
                                const int row = mbase + mt * 16 + lq + ((c >> 1) << 3);
                                const int col = nbase + nt * 8 + lr * 2 + (c & 1);
                                outb[SWF(row, col)] = to_tf32(fmaxf(ov, 0.f));
                            }
                        }
            }
        }

        __syncthreads();
        // ---- final layer ----
        if (tid < 64) {
            float sum = __ldg(p.b4[h]);
            const float* W4 = p.W4[h];
            const float* hb = smem + 4 * (ACT_B / 4);
            #pragma unroll
            for (int j = 0; j < 64; j++)
                sum = fmaf(hb[SWF(tid, j)], __ldg(W4 + j), sum);
            p.out[(size_t)h * BATCH + row0 + tid] = sum;
        }
        __syncthreads();
    }
}

extern "C" void kernel_launch(void* const* d_in, const int* in_sizes, int n_in,
                              void* d_out, int out_size) {
    (void)in_sizes; (void)n_in; (void)out_size;
    Params p;
    p.x    = (const float*)d_in[0];
    p.u    = (const float*)d_in[1];
    p.mixf = (const float*)d_in[2];
    p.P    = (const float*)d_in[3];
    for (int h = 0; h < 2; h++) {
        const int base = 4 + h * 8;
        p.W[h][0]  = (const float*)d_in[base + 0];
        p.Bb[h][0] = (const float*)d_in[base + 1];
        p.W[h][1]  = (const float*)d_in[base + 2];
        p.Bb[h][1] = (const float*)d_in[base + 3];
        p.W[h][2]  = (const float*)d_in[base + 4];
        p.Bb[h][2] = (const float*)d_in[base + 5];
        p.W4[h]    = (const float*)d_in[base + 6];
        p.b4[h]    = (const float*)d_in[base + 7];
        const int tbase = 20 + h * 6;
        p.tW[h][0] = (const float*)d_in[tbase + 0];
        p.tb[h][0] = (const float*)d_in[tbase + 1];
        p.tW[h][1] = (const float*)d_in[tbase + 2];
        p.tb[h][1] = (const float*)d_in[tbase + 3];
        p.tW[h][2] = (const float*)d_in[tbase + 4];
        p.tb[h][2] = (const float*)d_in[tbase + 5];
    }
    p.out = (float*)d_out;

    prep_kernel<<<(30 * 4096 + 960 + 255) / 256, 256>>>(p);
    cudaFuncSetAttribute(critic_main,
                         cudaFuncAttributeMaxDynamicSharedMemorySize, SMEM_BYTES);
    critic_main<<<NBLK, THREADS, SMEM_BYTES>>>(p);
}

// round 7
// speedup vs baseline: 2.1346x; 2.1346x over previous
#include <cuda_runtime.h>
#include <cuda_fp16.h>
#include <cstdint>
#include <cstddef>

// ---------------------------------------------------------------------------
// Critic_Mix fused kernel (round 6): fp16 m16n8k16 mma.sync (fp32 accumulate),
// ldmatrix.x4 fragments, preprocessed fp16 weight images, DOUBLE-BUFFERED
// weight SMEM with cp.async prefetch 2 streams ahead (wait_group 1).
// fp16 mantissa == tf32 mantissa (10 bits) -> same error profile, half the
// crossbar bytes and half the MMA instructions of the tf32 version.
// ---------------------------------------------------------------------------

#define THREADS   256
#define BM        64
#define BATCH     262144
#define NBLK      (BATCH / BM)

#define ACT_B      16384                 // 64 rows x 256B (128 fp16)
#define WBUF_B     32768                 // 128 rows x 256B fp16
#define WBUF_OFF   (5 * ACT_B)           // 81920
#define BIAS_OFF   (WBUF_OFF + 2 * WBUF_B)   // 147456
#define SMEM_BYTES (BIAS_OFF + 2048)     // 149504  (4 bias slots x 512B)

// Preprocessed fp16 weight images: 30 x 32KB, swizzled; biases fp32 padded.
__device__ uint4 g_wimg[30 * 2048];
__device__ float g_bimg[30 * 128];

struct Params {
    const float* x;
    const float* u;
    const float* mixf;
    const float* P;
    const float* W[2][3];
    const float* Bb[2][3];
    const float* W4[2];
    const float* b4[2];
    const float* tW[2][3];
    const float* tb[2][3];
    float*       out;
};

__device__ __forceinline__ uint32_t s2u(const void* p) {
    uint32_t a;
    asm("{ .reg .u64 t; cvta.to.shared.u64 t, %1; cvt.u32.u64 %0, t; }"
        : "=r"(a) : "l"(p));
    return a;
}
__device__ __forceinline__ void ldsm4(uint32_t* r, uint32_t addr) {
    asm volatile("ldmatrix.sync.aligned.m8n8.x4.shared.b16 {%0,%1,%2,%3}, [%4];"
                 : "=r"(r[0]), "=r"(r[1]), "=r"(r[2]), "=r"(r[3]) : "r"(addr));
}
__device__ __forceinline__ void mma16(float* c, const uint32_t* a,
                                      uint32_t b0, uint32_t b1) {
    asm volatile(
        "mma.sync.aligned.m16n8k16.row.col.f32.f16.f16.f32 "
        "{%0,%1,%2,%3}, {%4,%5,%6,%7}, {%8,%9}, {%0,%1,%2,%3};"
        : "+f"(c[0]), "+f"(c[1]), "+f"(c[2]), "+f"(c[3])
        : "r"(a[0]), "r"(a[1]), "r"(a[2]), "r"(a[3]), "r"(b0), "r"(b1));
}
__device__ __forceinline__ void cpasync16(uint32_t dst, const void* src) {
    asm volatile("cp.async.cg.shared.global [%0], [%1], 16;"
                 :: "r"(dst), "l"(src) : "memory");
}

// ---------------- preprocessing kernel ----------------
// Weight image layout: row n (output idx) = 256B; 16B chunk ch at
// byte n*256 + ((ch ^ (n&7)) << 4). O=64 images: rows 64..127 zero
// (and never fetched: rows 0..63 = first 16KB, contiguous).
__global__ void prep_kernel(Params p) {
    const int idx = blockIdx.x * 256 + threadIdx.x;
    if (idx < 30 * 2048) {
        const int img = idx >> 11, rem = idx & 2047;
        const int n = rem >> 4, ch = rem & 15;
        const int h = img / 15, rr = img % 15, L = rr / 5, s = rr % 5;
        const int O = (L == 2) ? 64 : 128;
        uint4 o = make_uint4(0u, 0u, 0u, 0u);
        if (n < O) {
            const float* W = (s == 4) ? p.W[h][L]
                                      : p.tW[h][L] + (size_t)s * O * 128;
            const float4 v0 = *reinterpret_cast<const float4*>(W + (size_t)n * 128 + ch * 8);
            const float4 v1 = *reinterpret_cast<const float4*>(W + (size_t)n * 128 + ch * 8 + 4);
            __half2 t0 = __floats2half2_rn(v0.x, v0.y);
            __half2 t1 = __floats2half2_rn(v0.z, v0.w);
            __half2 t2 = __floats2half2_rn(v1.x, v1.y);
            __half2 t3 = __floats2half2_rn(v1.z, v1.w);
            o.x = *reinterpret_cast<uint32_t*>(&t0);
            o.y = *reinterpret_cast<uint32_t*>(&t1);
            o.z = *reinterpret_cast<uint32_t*>(&t2);
            o.w = *reinterpret_cast<uint32_t*>(&t3);
        }
        g_wimg[img * 2048 + n * 16 + (ch ^ (n & 7))] = o;
    } else if (idx < 30 * 2048 + 960) {
        const int b = idx - 30 * 2048;
        const int img = b >> 5, q = b & 31;
        const int h = img / 15, rr = img % 15, L = rr / 5, s = rr % 5;
        const int O = (L == 2) ? 64 : 128;
        const float* B = (s == 4) ? p.Bb[h][L] : p.tb[h][L] + s * O;
        const int o = q * 4;
        float4 v;
        v.x = (o + 0 < O) ? B[o + 0] : 0.f;
        v.y = (o + 1 < O) ? B[o + 1] : 0.f;
        v.z = (o + 2 < O) ? B[o + 2] : 0.f;
        v.w = (o + 3 < O) ? B[o + 3] : 0.f;
        *reinterpret_cast<float4*>(g_bimg + img * 128 + o) = v;
    }
}

// ---------------- main kernel ----------------
__device__ __forceinline__ void prefetch_img(uint32_t wbuf_u, uint32_t bias_u,
                                             int img, int wslot, int bslot, int tid) {
    const uint4* src = g_wimg + img * 2048;
    const int nv = (((img % 15) / 5) == 2) ? 4 : 8;   // L=2: 16KB only
    const uint32_t dst = wbuf_u + (uint32_t)wslot * WBUF_B;
    #pragma unroll
    for (int i = 0; i < 8; i++)
        if (i < nv)
            cpasync16(dst + (uint32_t)(tid + i * 256) * 16, src + tid + i * 256);
    if (tid < 32)
        cpasync16(bias_u + (uint32_t)bslot * 512 + tid * 16,
                  reinterpret_cast<const float4*>(g_bimg + img * 128) + tid);
    asm volatile("cp.async.commit_group;" ::: "memory");
}

__global__ void __launch_bounds__(THREADS, 1)
critic_main(Params p) {
    extern __shared__ char smem[];
    const uint32_t sbase  = s2u(smem);
    const uint32_t wbuf_u = sbase + WBUF_OFF;
    const uint32_t bias_u = sbase + BIAS_OFF;
    float* biasf = reinterpret_cast<float*>(smem + BIAS_OFF);

    const int tid  = threadIdx.x;
    const int lane = tid & 31;
    const int wid  = tid >> 5;
    const int wm   = wid & 1;
    const int wn   = wid >> 1;
    const int mbase = wm * 32;
    const int nbase = wn * 32;
    const int lq = lane >> 2, lr = lane & 3;
    const int r8 = lane & 7, sel = lane >> 3;
    const int row0 = blockIdx.x * BM;
    const bool lowN = (wn < 2);

    // ldmatrix x4 address components (fp16, 256B rows, chunk XOR swizzle).
    // A: m0/m1 rows +0/+8 (sel&1), m2/m3 chunk +1 (sel>>1).
    // B: m0/m1 chunk +0/+1 (sel&1), m2/m3 rows +8 (sel>>1).
    const int rA0 = mbase + (sel & 1) * 8 + r8;            // rA&7 == r8
    const int rB0 = nbase + (sel >> 1) * 8 + r8;
    const uint32_t eA4 = (uint32_t)(((sel >> 1) ^ r8) << 4);
    const uint32_t eB4 = (uint32_t)(((sel & 1) ^ r8) << 4);
    const uint32_t aoff0 = (uint32_t)rA0 * 256;
    const uint32_t aoff1 = aoff0 + 16 * 256;
    const uint32_t boffr0 = (uint32_t)rB0 * 256;
    const uint32_t boffr1 = boffr0 + 16 * 256;

    const float m = __ldg(p.mixf);
    const float inv_m = 1.0f - m;
    float Pk[4];
    #pragma unroll
    for (int k = 0; k < 4; k++) Pk[k] = __ldg(p.P + k);

    // Prime the 2-deep weight pipeline.
    prefetch_img(wbuf_u, bias_u, 0, 0, 0, tid);
    prefetch_img(wbuf_u, bias_u, 1, 1, 1, tid);

    for (int h = 0; h < 2; h++) {
        // ---- xu -> act buffer 4 (fp16, swizzled) ----
        {
            char* dst = smem + 4 * ACT_B;
            #pragma unroll
            for (int i = tid; i < 1024; i += THREADS) {
                const int r = i >> 4, ch = i & 15;
                float4 v0, v1;
                if (ch < 12) {
                    const float* src = p.x + (size_t)(row0 + r) * 96 + ch * 8;
                    v0 = *reinterpret_cast<const float4*>(src);
                    v1 = *reinterpret_cast<const float4*>(src + 4);
                } else {
                    const float* src = p.u + (size_t)(row0 + r) * 32 + (ch - 12) * 8;
                    v0 = *reinterpret_cast<const float4*>(src);
                    v1 = *reinterpret_cast<const float4*>(src + 4);
                }
                __half2 t0 = __floats2half2_rn(v0.x, v0.y);
                __half2 t1 = __floats2half2_rn(v0.z, v0.w);
                __half2 t2 = __floats2half2_rn(v1.x, v1.y);
                __half2 t3 = __floats2half2_rn(v1.z, v1.w);
                uint4 o;
                o.x = *reinterpret_cast<uint32_t*>(&t0);
                o.y = *reinterpret_cast<uint32_t*>(&t1);
                o.z = *reinterpret_cast<uint32_t*>(&t2);
                o.w = *reinterpret_cast<uint32_t*>(&t3);
                *reinterpret_cast<uint4*>(dst + r * 256 + ((ch ^ (r & 7)) << 4)) = o;
            }
        }

        float mix[2][4][4];
        for (int t = 0; t < 15; t++) {
            const int g = h * 15 + t;
            const int L = t / 5, s = t % 5;
            const bool is_main = (s == 4);
            const bool active  = (L < 2) || lowN;
            if (s == 0) {
                #pragma unroll
                for (int mt = 0; mt < 2; mt++)
                    #pragma unroll
                    for (int nt = 0; nt < 4; nt++)
                        #pragma unroll
                        for (int c = 0; c < 4; c++) mix[mt][nt][c] = 0.f;
            }

            // group for stream g complete (group g+1 may stay in flight)
            asm volatile("cp.async.wait_group 1;" ::: "memory");
            __syncthreads();

            float acc[2][4][4];
            #pragma unroll
            for (int mt = 0; mt < 2; mt++)
                #pragma unroll
                for (int nt = 0; nt < 4; nt++)
                    #pragma unroll
                    for (int c = 0; c < 4; c++) acc[mt][nt][c] = 0.f;

            if (active) {
                const int inb = (L == 0) ? 4 : (is_main ? 4 : s);
                const uint32_t ab0 = sbase + (uint32_t)inb * ACT_B + aoff0;
                const uint32_t ab1 = sbase + (uint32_t)inb * ACT_B + aoff1;
                const uint32_t wb  = wbuf_u + (uint32_t)(g & 1) * WBUF_B;
                const uint32_t bb0 = wb + boffr0;
                const uint32_t bb1 = wb + boffr1;

                uint32_t fa0[2][4], fa1[2][4], fb0[2][4], fb1[2][4];
                ldsm4(fa0[0], ab0 + eA4);
                ldsm4(fa1[0], ab1 + eA4);
                ldsm4(fb0[0], bb0 + eB4);
                ldsm4(fb1[0], bb1 + eB4);
                #pragma unroll
                for (int j = 0; j < 8; j++) {
                    const int cur = j & 1, nxt = cur ^ 1;
                    if (j < 7) {
                        const uint32_t tA = ((uint32_t)((j + 1) << 5)) ^ eA4;
                        const uint32_t tB = ((uint32_t)((j + 1) << 5)) ^ eB4;
                        ldsm4(fa0[nxt], ab0 + tA);
                        ldsm4(fa1[nxt], ab1 + tA);
                        ldsm4(fb0[nxt], bb0 + tB);
                        ldsm4(fb1[nxt], bb1 + tB);
                    }
                    mma16(acc[0][0], fa0[cur], fb0[cur][0], fb0[cur][1]);
                    mma16(acc[0][1], fa0[cur], fb0[cur][2], fb0[cur][3]);
                    mma16(acc[0][2], fa0[cur], fb1[cur][0], fb1[cur][1]);
                    mma16(acc[0][3], fa0[cur], fb1[cur][2], fb1[cur][3]);
                    mma16(acc[1][0], fa1[cur], fb0[cur][0], fb0[cur][1]);
                    mma16(acc[1][1], fa1[cur], fb0[cur][2], fb0[cur][3]);
                    mma16(acc[1][2], fa1[cur], fb1[cur][0], fb1[cur][1]);
                    mma16(acc[1][3], fa1[cur], fb1[cur][2], fb1[cur][3]);
                }
            }

            __syncthreads();    // wbuf[g&1] + act reads done

            // prefetch stream g+2 into wbuf[(g+2)&1] (just-freed slot) and
            // bias slot (g+2)&3 (disjoint from this stream's g&3).
            prefetch_img(wbuf_u, bias_u, (g + 2) % 30, (g + 2) & 1,
                         (g + 2) & 3, tid);

            if (active) {
                const float sc = is_main ? inv_m : (m * Pk[s]);
                const float* bs = biasf + (g & 3) * 128;
                float bias[4][2];
                #pragma unroll
                for (int nt = 0; nt < 4; nt++) {
                    bias[nt][0] = bs[nbase + nt * 8 + lr * 2 + 0];
                    bias[nt][1] = bs[nbase + nt * 8 + lr * 2 + 1];
                }
                const bool do_store = is_main || (L < 2);
                char* outb = smem + (is_main ? 4 : s) * ACT_B;
                #pragma unroll
                for (int mt = 0; mt < 2; mt++)
                    #pragma unroll
                    for (int nt = 0; nt < 4; nt++)
                        #pragma unroll
                        for (int c2 = 0; c2 < 2; c2++) {   // c2 = c>>1 (row +8)
                            const float v0 = acc[mt][nt][c2 * 2 + 0] + bias[nt][0];
                            const float v1 = acc[mt][nt][c2 * 2 + 1] + bias[nt][1];
                            float o0, o1;
                            if (!is_main) {
                                mix[mt][nt][c2 * 2 + 0] = fmaf(sc, v0, mix[mt][nt][c2 * 2 + 0]);
                                mix[mt][nt][c2 * 2 + 1] = fmaf(sc, v1, mix[mt][nt][c2 * 2 + 1]);
                                o0 = v0; o1 = v1;
                            } else {
                                o0 = fmaf(sc, v0, mix[mt][nt][c2 * 2 + 0]);
                                o1 = fmaf(sc, v1, mix[mt][nt][c2 * 2 + 1]);
                            }
                            if (do_store) {
                                const int row = mbase + mt * 16 + lq + c2 * 8;
                                __half2 hv = __floats2half2_rn(fmaxf(o0, 0.f),
                                                               fmaxf(o1, 0.f));
                                *reinterpret_cast<uint32_t*>(
                                    outb + row * 256 +
                                    ((((nbase >> 3) + nt) ^ (row & 7)) << 4) +
                                    lr * 4) = *reinterpret_cast<uint32_t*>(&hv);
                            }
                        }
            }
        }

        __syncthreads();
        // ---- final layer: out = h3 . W4 + b4 (fp16 act from buf4) ----
        if (tid < 64) {
            float sum = __ldg(p.b4[h]);
            const float* W4 = p.W4[h];
            const char* hb = smem + 4 * ACT_B;
            #pragma unroll
            for (int k2 = 0; k2 < 64; k2++) {
                const __half hv = *reinterpret_cast<const __half*>(
                    hb + tid * 256 + (((k2 >> 3) ^ (tid & 7)) << 4) + (k2 & 7) * 2);
                sum = fmaf(__half2float(hv), __ldg(W4 + k2), sum);
            }
            p.out[(size_t)h * BATCH + row0 + tid] = sum;
        }
        __syncthreads();   // buf4 free before next head's xu reload
    }
}

extern "C" void kernel_launch(void* const* d_in, const int* in_sizes, int n_in,
                              void* d_out, int out_size) {
    (void)in_sizes; (void)n_in; (void)out_size;
    Params p;
    p.x    = (const float*)d_in[0];
    p.u    = (const float*)d_in[1];
    p.mixf = (const float*)d_in[2];
    p.P    = (const float*)d_in[3];
    for (int h = 0; h < 2; h++) {
        const int base = 4 + h * 8;
        p.W[h][0]  = (const float*)d_in[base + 0];
        p.Bb[h][0] = (const float*)d_in[base + 1];
        p.W[h][1]  = (const float*)d_in[base + 2];
        p.Bb[h][1] = (const float*)d_in[base + 3];
        p.W[h][2]  = (const float*)d_in[base + 4];
        p.Bb[h][2] = (const float*)d_in[base + 5];
        p.W4[h]    = (const float*)d_in[base + 6];
        p.b4[h]    = (const float*)d_in[base + 7];
        const int tbase = 20 + h * 6;
        p.tW[h][0] = (const float*)d_in[tbase + 0];
        p.tb[h][0] = (const float*)d_in[tbase + 1];
        p.tW[h][1] = (const float*)d_in[tbase + 2];
        p.tb[h][1] = (const float*)d_in[tbase + 3];
        p.tW[h][2] = (const float*)d_in[tbase + 4];
        p.tb[h][2] = (const float*)d_in[tbase + 5];
    }
    p.out = (float*)d_out;

    prep_kernel<<<(30 * 2048 + 960 + 255) / 256, 256>>>(p);
    cudaFuncSetAttribute(critic_main,
                         cudaFuncAttributeMaxDynamicSharedMemorySize, SMEM_BYTES);
    critic_main<<<NBLK, THREADS, SMEM_BYTES>>>(p);
}

// round 8
// speedup vs baseline: 2.5163x; 1.1788x over previous
#include <cuda_runtime.h>
#include <cuda_fp16.h>
#include <cstdint>
#include <cstddef>

// ---------------------------------------------------------------------------
// Critic_Mix fused kernel (round 7): fp16 m16n8k16 mma.sync, BM=128 rows/CTA,
// 512 threads (4x4 warp grid of independent 32x32 tiles), double-buffered
// weight SMEM via cp.async 2 streams ahead. Per-row crossbar traffic equal to
// R6, weight L2 traffic and barrier count halved, warp concurrency doubled.
// ---------------------------------------------------------------------------

#define THREADS   512
#define BM        128
#define BATCH     262144
#define NBLK      (BATCH / BM)

#define ACT_B      32768                 // 128 rows x 256B (128 fp16)
#define WBUF_B     32768                 // 128 rows x 256B fp16
#define WBUF_OFF   (5 * ACT_B)           // 163840
#define BIAS_OFF   (WBUF_OFF + 2 * WBUF_B)   // 229376
#define SMEM_BYTES (BIAS_OFF + 2048)     // 231424 <= 232448

// Preprocessed fp16 weight images: 30 x 32KB, swizzled; biases fp32 padded.
__device__ uint4 g_wimg[30 * 2048];
__device__ float g_bimg[30 * 128];

struct Params {
    const float* x;
    const float* u;
    const float* mixf;
    const float* P;
    const float* W[2][3];
    const float* Bb[2][3];
    const float* W4[2];
    const float* b4[2];
    const float* tW[2][3];
    const float* tb[2][3];
    float*       out;
};

__device__ __forceinline__ uint32_t s2u(const void* p) {
    uint32_t a;
    asm("{ .reg .u64 t; cvta.to.shared.u64 t, %1; cvt.u32.u64 %0, t; }"
        : "=r"(a) : "l"(p));
    return a;
}
__device__ __forceinline__ void ldsm4(uint32_t* r, uint32_t addr) {
    asm volatile("ldmatrix.sync.aligned.m8n8.x4.shared.b16 {%0,%1,%2,%3}, [%4];"
                 : "=r"(r[0]), "=r"(r[1]), "=r"(r[2]), "=r"(r[3]) : "r"(addr));
}
__device__ __forceinline__ void mma16(float* c, const uint32_t* a,
                                      uint32_t b0, uint32_t b1) {
    asm volatile(
        "mma.sync.aligned.m16n8k16.row.col.f32.f16.f16.f32 "
        "{%0,%1,%2,%3}, {%4,%5,%6,%7}, {%8,%9}, {%0,%1,%2,%3};"
        : "+f"(c[0]), "+f"(c[1]), "+f"(c[2]), "+f"(c[3])
        : "r"(a[0]), "r"(a[1]), "r"(a[2]), "r"(a[3]), "r"(b0), "r"(b1));
}
__device__ __forceinline__ void cpasync16(uint32_t dst, const void* src) {
    asm volatile("cp.async.cg.shared.global [%0], [%1], 16;"
                 :: "r"(dst), "l"(src) : "memory");
}

// ---------------- preprocessing kernel ----------------
// Weight image: row n = 256B; 16B chunk ch at byte n*256 + ((ch^(n&7))<<4).
// O=64 images: rows 64..127 zero and never fetched (first 16KB contiguous).
__global__ void prep_kernel(Params p) {
    const int idx = blockIdx.x * 256 + threadIdx.x;
    if (idx < 30 * 2048) {
        const int img = idx >> 11, rem = idx & 2047;
        const int n = rem >> 4, ch = rem & 15;
        const int h = img / 15, rr = img % 15, L = rr / 5, s = rr % 5;
        const int O = (L == 2) ? 64 : 128;
        uint4 o = make_uint4(0u, 0u, 0u, 0u);
        if (n < O) {
            const float* W = (s == 4) ? p.W[h][L]
                                      : p.tW[h][L] + (size_t)s * O * 128;
            const float4 v0 = *reinterpret_cast<const float4*>(W + (size_t)n * 128 + ch * 8);
            const float4 v1 = *reinterpret_cast<const float4*>(W + (size_t)n * 128 + ch * 8 + 4);
            __half2 t0 = __floats2half2_rn(v0.x, v0.y);
            __half2 t1 = __floats2half2_rn(v0.z, v0.w);
            __half2 t2 = __floats2half2_rn(v1.x, v1.y);
            __half2 t3 = __floats2half2_rn(v1.z, v1.w);
            o.x = *reinterpret_cast<uint32_t*>(&t0);
            o.y = *reinterpret_cast<uint32_t*>(&t1);
            o.z = *reinterpret_cast<uint32_t*>(&t2);
            o.w = *reinterpret_cast<uint32_t*>(&t3);
        }
        g_wimg[img * 2048 + n * 16 + (ch ^ (n & 7))] = o;
    } else if (idx < 30 * 2048 + 960) {
        const int b = idx - 30 * 2048;
        const int img = b >> 5, q = b & 31;
        const int h = img / 15, rr = img % 15, L = rr / 5, s = rr % 5;
        const int O = (L == 2) ? 64 : 128;
        const float* B = (s == 4) ? p.Bb[h][L] : p.tb[h][L] + s * O;
        const int o = q * 4;
        float4 v;
        v.x = (o + 0 < O) ? B[o + 0] : 0.f;
        v.y = (o + 1 < O) ? B[o + 1] : 0.f;
        v.z = (o + 2 < O) ? B[o + 2] : 0.f;
        v.w = (o + 3 < O) ? B[o + 3] : 0.f;
        *reinterpret_cast<float4*>(g_bimg + img * 128 + o) = v;
    }
}

// ---------------- main kernel ----------------
__device__ __forceinline__ void prefetch_img(uint32_t wbuf_u, uint32_t bias_u,
                                             int img, int wslot, int bslot, int tid) {
    const uint4* src = g_wimg + img * 2048;
    const int nv = (((img % 15) / 5) == 2) ? 2 : 4;   // L=2: 16KB only
    const uint32_t dst = wbuf_u + (uint32_t)wslot * WBUF_B;
    #pragma unroll
    for (int i = 0; i < 4; i++)
        if (i < nv)
            cpasync16(dst + (uint32_t)(tid + i * 512) * 16, src + tid + i * 512);
    if (tid < 32)
        cpasync16(bias_u + (uint32_t)bslot * 512 + tid * 16,
                  reinterpret_cast<const float4*>(g_bimg + img * 128) + tid);
    asm volatile("cp.async.commit_group;" ::: "memory");
}

__global__ void __launch_bounds__(THREADS, 1)
critic_main(Params p) {
    extern __shared__ char smem[];
    const uint32_t sbase  = s2u(smem);
    const uint32_t wbuf_u = sbase + WBUF_OFF;
    const uint32_t bias_u = sbase + BIAS_OFF;
    float* biasf = reinterpret_cast<float*>(smem + BIAS_OFF);

    const int tid  = threadIdx.x;
    const int lane = tid & 31;
    const int wid  = tid >> 5;          // 0..15
    const int wm   = wid & 3;           // 4 warps over m (batch, 32 rows each)
    const int wn   = wid >> 2;          // 4 warps over n (outputs, 32 each)
    const int mbase = wm * 32;
    const int nbase = wn * 32;
    const int lq = lane >> 2, lr = lane & 3;
    const int r8 = lane & 7, sel = lane >> 3;
    const int row0 = blockIdx.x * BM;
    const bool lowN = (wn < 2);

    const int rA0 = mbase + (sel & 1) * 8 + r8;
    const int rB0 = nbase + (sel >> 1) * 8 + r8;
    const uint32_t eA4 = (uint32_t)(((sel >> 1) ^ r8) << 4);
    const uint32_t eB4 = (uint32_t)(((sel & 1) ^ r8) << 4);
    const uint32_t aoff0 = (uint32_t)rA0 * 256;
    const uint32_t aoff1 = aoff0 + 16 * 256;
    const uint32_t boffr0 = (uint32_t)rB0 * 256;
    const uint32_t boffr1 = boffr0 + 16 * 256;

    const float m = __ldg(p.mixf);
    const float inv_m = 1.0f - m;
    float Pk[4];
    #pragma unroll
    for (int k = 0; k < 4; k++) Pk[k] = __ldg(p.P + k);

    // Prime the 2-deep weight pipeline.
    prefetch_img(wbuf_u, bias_u, 0, 0, 0, tid);
    prefetch_img(wbuf_u, bias_u, 1, 1, 1, tid);

    for (int h = 0; h < 2; h++) {
        // ---- xu -> act buffer 4 (fp16, swizzled) ----
        {
            char* dst = smem + 4 * ACT_B;
            #pragma unroll
            for (int i = tid; i < BM * 16; i += THREADS) {
                const int r = i >> 4, ch = i & 15;
                float4 v0, v1;
                if (ch < 12) {
                    const float* src = p.x + (size_t)(row0 + r) * 96 + ch * 8;
                    v0 = *reinterpret_cast<const float4*>(src);
                    v1 = *reinterpret_cast<const float4*>(src + 4);
                } else {
                    const float* src = p.u + (size_t)(row0 + r) * 32 + (ch - 12) * 8;
                    v0 = *reinterpret_cast<const float4*>(src);
                    v1 = *reinterpret_cast<const float4*>(src + 4);
                }
                __half2 t0 = __floats2half2_rn(v0.x, v0.y);
                __half2 t1 = __floats2half2_rn(v0.z, v0.w);
                __half2 t2 = __floats2half2_rn(v1.x, v1.y);
                __half2 t3 = __floats2half2_rn(v1.z, v1.w);
                uint4 o;
                o.x = *reinterpret_cast<uint32_t*>(&t0);
                o.y = *reinterpret_cast<uint32_t*>(&t1);
                o.z = *reinterpret_cast<uint32_t*>(&t2);
                o.w = *reinterpret_cast<uint32_t*>(&t3);
                *reinterpret_cast<uint4*>(dst + r * 256 + ((ch ^ (r & 7)) << 4)) = o;
            }
        }

        float mix[2][4][4];
        for (int t = 0; t < 15; t++) {
            const int g = h * 15 + t;
            const int L = t / 5, s = t % 5;
            const bool is_main = (s == 4);
            const bool active  = (L < 2) || lowN;
            if (s == 0) {
                #pragma unroll
                for (int mt = 0; mt < 2; mt++)
                    #pragma unroll
                    for (int nt = 0; nt < 4; nt++)
                        #pragma unroll
                        for (int c = 0; c < 4; c++) mix[mt][nt][c] = 0.f;
            }

            asm volatile("cp.async.wait_group 1;" ::: "memory");
            __syncthreads();

            float acc[2][4][4];
            #pragma unroll
            for (int mt = 0; mt < 2; mt++)
                #pragma unroll
                for (int nt = 0; nt < 4; nt++)
                    #pragma unroll
                    for (int c = 0; c < 4; c++) acc[mt][nt][c] = 0.f;

            if (active) {
                const int inb = (L == 0) ? 4 : (is_main ? 4 : s);
                const uint32_t ab0 = sbase + (uint32_t)inb * ACT_B + aoff0;
                const uint32_t ab1 = sbase + (uint32_t)inb * ACT_B + aoff1;
                const uint32_t wb  = wbuf_u + (uint32_t)(g & 1) * WBUF_B;
                const uint32_t bb0 = wb + boffr0;
                const uint32_t bb1 = wb + boffr1;

                #pragma unroll
                for (int j = 0; j < 8; j++) {
                    const uint32_t tA = ((uint32_t)(j << 5)) ^ eA4;
                    const uint32_t tB = ((uint32_t)(j << 5)) ^ eB4;
                    uint32_t fa0[4], fa1[4], fb0[4], fb1[4];
                    ldsm4(fa0, ab0 + tA);
                    ldsm4(fa1, ab1 + tA);
                    ldsm4(fb0, bb0 + tB);
                    ldsm4(fb1, bb1 + tB);
                    mma16(acc[0][0], fa0, fb0[0], fb0[1]);
                    mma16(acc[0][1], fa0, fb0[2], fb0[3]);
                    mma16(acc[0][2], fa0, fb1[0], fb1[1]);
                    mma16(acc[0][3], fa0, fb1[2], fb1[3]);
                    mma16(acc[1][0], fa1, fb0[0], fb0[1]);
                    mma16(acc[1][1], fa1, fb0[2], fb0[3]);
                    mma16(acc[1][2], fa1, fb1[0], fb1[1]);
                    mma16(acc[1][3], fa1, fb1[2], fb1[3]);
                }
            }

            __syncthreads();    // wbuf[g&1] + act reads done

            prefetch_img(wbuf_u, bias_u, (g + 2) % 30, (g + 2) & 1,
                         (g + 2) & 3, tid);

            if (active) {
                const float sc = is_main ? inv_m : (m * Pk[s]);
                const float* bs = biasf + (g & 3) * 128;
                float bias[4][2];
                #pragma unroll
                for (int nt = 0; nt < 4; nt++) {
                    bias[nt][0] = bs[nbase + nt * 8 + lr * 2 + 0];
                    bias[nt][1] = bs[nbase + nt * 8 + lr * 2 + 1];
                }
                const bool do_store = is_main || (L < 2);
                char* outb = smem + (is_main ? 4 : s) * ACT_B;
                #pragma unroll
                for (int mt = 0; mt < 2; mt++)
                    #pragma unroll
                    for (int nt = 0; nt < 4; nt++)
                        #pragma unroll
                        for (int c2 = 0; c2 < 2; c2++) {
                            const float v0 = acc[mt][nt][c2 * 2 + 0] + bias[nt][0];
                            const float v1 = acc[mt][nt][c2 * 2 + 1] + bias[nt][1];
                            float o0, o1;
                            if (!is_main) {
                                mix[mt][nt][c2 * 2 + 0] = fmaf(sc, v0, mix[mt][nt][c2 * 2 + 0]);
                                mix[mt][nt][c2 * 2 + 1] = fmaf(sc, v1, mix[mt][nt][c2 * 2 + 1]);
                                o0 = v0; o1 = v1;
                            } else {
                                o0 = fmaf(sc, v0, mix[mt][nt][c2 * 2 + 0]);
                                o1 = fmaf(sc, v1, mix[mt][nt][c2 * 2 + 1]);
                            }
                            if (do_store) {
                                const int row = mbase + mt * 16 + lq + c2 * 8;
                                __half2 hv = __floats2half2_rn(fmaxf(o0, 0.f),
                                                               fmaxf(o1, 0.f));
                                *reinterpret_cast<uint32_t*>(
                                    outb + row * 256 +
                                    ((((nbase >> 3) + nt) ^ (row & 7)) << 4) +
                                    lr * 4) = *reinterpret_cast<uint32_t*>(&hv);
                            }
                        }
            }
        }

        __syncthreads();
        // ---- final layer: out = h3 . W4 + b4 ----
        if (tid < BM) {
            float sum = __ldg(p.b4[h]);
            const float* W4 = p.W4[h];
            const char* hb = smem + 4 * ACT_B;
            #pragma unroll
            for (int k2 = 0; k2 < 64; k2++) {
                const __half hv = *reinterpret_cast<const __half*>(
                    hb + tid * 256 + (((k2 >> 3) ^ (tid & 7)) << 4) + (k2 & 7) * 2);
                sum = fmaf(__half2float(hv), __ldg(W4 + k2), sum);
            }
            p.out[(size_t)h * BATCH + row0 + tid] = sum;
        }
        __syncthreads();   // buf4 free before next head's xu reload
    }
}

extern "C" void kernel_launch(void* const* d_in, const int* in_sizes, int n_in,
                              void* d_out, int out_size) {
    (void)in_sizes; (void)n_in; (void)out_size;
    Params p;
    p.x    = (const float*)d_in[0];
    p.u    = (const float*)d_in[1];
    p.mixf = (const float*)d_in[2];
    p.P    = (const float*)d_in[3];
    for (int h = 0; h < 2; h++) {
        const int base = 4 + h * 8;
        p.W[h][0]  = (const float*)d_in[base + 0];
        p.Bb[h][0] = (const float*)d_in[base + 1];
        p.W[h][1]  = (const float*)d_in[base + 2];
        p.Bb[h][1] = (const float*)d_in[base + 3];
        p.W[h][2]  = (const float*)d_in[base + 4];
        p.Bb[h][2] = (const float*)d_in[base + 5];
        p.W4[h]    = (const float*)d_in[base + 6];
        p.b4[h]    = (const float*)d_in[base + 7];
        const int tbase = 20 + h * 6;
        p.tW[h][0] = (const float*)d_in[tbase + 0];
        p.tb[h][0] = (const float*)d_in[tbase + 1];
        p.tW[h][1] = (const float*)d_in[tbase + 2];
        p.tb[h][1] = (const float*)d_in[tbase + 3];
        p.tW[h][2] = (const float*)d_in[tbase + 4];
        p.tb[h][2] = (const float*)d_in[tbase + 5];
    }
    p.out = (float*)d_out;

    prep_kernel<<<(30 * 2048 + 960 + 255) / 256, 256>>>(p);
    cudaFuncSetAttribute(critic_main,
                         cudaFuncAttributeMaxDynamicSharedMemorySize, SMEM_BYTES);
    critic_main<<<NBLK, THREADS, SMEM_BYTES>>>(p);
}

// round 9
// speedup vs baseline: 2.8111x; 1.1172x over previous
#include <cuda_runtime.h>
#include <cuda_fp16.h>
#include <cstdint>
#include <cstddef>

// ---------------------------------------------------------------------------
// Critic_Mix fused kernel (round 8): fp16 m16n8k16 mma.sync, BM=64, 256 thr,
// 2 CTAs/SM (independent barrier domains cover each other's latency).
// Single 32KB weight buffer, cp.async prefetch next stream after k-loop.
// SMEM/CTA = 115,712 B so two CTAs co-reside; launch_bounds(256,2).
// ---------------------------------------------------------------------------

#define THREADS   256
#define BM        64
#define BATCH     262144
#define NBLK      (BATCH / BM)

#define ACT_B      16384                 // 64 rows x 256B (128 fp16)
#define WBUF_B     32768                 // 128 rows x 256B fp16
#define WBUF_OFF   (5 * ACT_B)           // 81920
#define BIAS_OFF   (WBUF_OFF + WBUF_B)   // 114688
#define SMEM_BYTES (BIAS_OFF + 1024)     // 115712 -> 2 CTAs/SM

// Preprocessed fp16 weight images: 30 x 32KB, swizzled; biases fp32 padded.
__device__ uint4 g_wimg[30 * 2048];
__device__ float g_bimg[30 * 128];

struct Params {
    const float* x;
    const float* u;
    const float* mixf;
    const float* P;
    const float* W[2][3];
    const float* Bb[2][3];
    const float* W4[2];
    const float* b4[2];
    const float* tW[2][3];
    const float* tb[2][3];
    float*       out;
};

__device__ __forceinline__ uint32_t s2u(const void* p) {
    uint32_t a;
    asm("{ .reg .u64 t; cvta.to.shared.u64 t, %1; cvt.u32.u64 %0, t; }"
        : "=r"(a) : "l"(p));
    return a;
}
__device__ __forceinline__ void ldsm4(uint32_t* r, uint32_t addr) {
    asm volatile("ldmatrix.sync.aligned.m8n8.x4.shared.b16 {%0,%1,%2,%3}, [%4];"
                 : "=r"(r[0]), "=r"(r[1]), "=r"(r[2]), "=r"(r[3]) : "r"(addr));
}
__device__ __forceinline__ void mma16(float* c, const uint32_t* a,
                                      uint32_t b0, uint32_t b1) {
    asm volatile(
        "mma.sync.aligned.m16n8k16.row.col.f32.f16.f16.f32 "
        "{%0,%1,%2,%3}, {%4,%5,%6,%7}, {%8,%9}, {%0,%1,%2,%3};"
        : "+f"(c[0]), "+f"(c[1]), "+f"(c[2]), "+f"(c[3])
        : "r"(a[0]), "r"(a[1]), "r"(a[2]), "r"(a[3]), "r"(b0), "r"(b1));
}
__device__ __forceinline__ void cpasync16(uint32_t dst, const void* src) {
    asm volatile("cp.async.cg.shared.global [%0], [%1], 16;"
                 :: "r"(dst), "l"(src) : "memory");
}

// ---------------- preprocessing kernel ----------------
// Weight image: row n = 256B; 16B chunk ch at byte n*256 + ((ch^(n&7))<<4).
// O=64 images: rows 64..127 zero and never fetched (first 16KB contiguous).
__global__ void prep_kernel(Params p) {
    const int idx = blockIdx.x * 256 + threadIdx.x;
    if (idx < 30 * 2048) {
        const int img = idx >> 11, rem = idx & 2047;
        const int n = rem >> 4, ch = rem & 15;
        const int h = img / 15, rr = img % 15, L = rr / 5, s = rr % 5;
        const int O = (L == 2) ? 64 : 128;
        uint4 o = make_uint4(0u, 0u, 0u, 0u);
        if (n < O) {
            const float* W = (s == 4) ? p.W[h][L]
                                      : p.tW[h][L] + (size_t)s * O * 128;
            const float4 v0 = *reinterpret_cast<const float4*>(W + (size_t)n * 128 + ch * 8);
            const float4 v1 = *reinterpret_cast<const float4*>(W + (size_t)n * 128 + ch * 8 + 4);
            __half2 t0 = __floats2half2_rn(v0.x, v0.y);
            __half2 t1 = __floats2half2_rn(v0.z, v0.w);
            __half2 t2 = __floats2half2_rn(v1.x, v1.y);
            __half2 t3 = __floats2half2_rn(v1.z, v1.w);
            o.x = *reinterpret_cast<uint32_t*>(&t0);
            o.y = *reinterpret_cast<uint32_t*>(&t1);
            o.z = *reinterpret_cast<uint32_t*>(&t2);
            o.w = *reinterpret_cast<uint32_t*>(&t3);
        }
        g_wimg[img * 2048 + n * 16 + (ch ^ (n & 7))] = o;
    } else if (idx < 30 * 2048 + 960) {
        const int b = idx - 30 * 2048;
        const int img = b >> 5, q = b & 31;
        const int h = img / 15, rr = img % 15, L = rr / 5, s = rr % 5;
        const int O = (L == 2) ? 64 : 128;
        const float* B = (s == 4) ? p.Bb[h][L] : p.tb[h][L] + s * O;
        const int o = q * 4;
        float4 v;
        v.x = (o + 0 < O) ? B[o + 0] : 0.f;
        v.y = (o + 1 < O) ? B[o + 1] : 0.f;
        v.z = (o + 2 < O) ? B[o + 2] : 0.f;
        v.w = (o + 3 < O) ? B[o + 3] : 0.f;
        *reinterpret_cast<float4*>(g_bimg + img * 128 + o) = v;
    }
}

// ---------------- main kernel ----------------
__device__ __forceinline__ void prefetch_img(uint32_t wbuf_u, uint32_t bias_u,
                                             int img, int bslot, int tid) {
    const uint4* src = g_wimg + img * 2048;
    const int nv = (((img % 15) / 5) == 2) ? 4 : 8;   // L=2: 16KB only
    #pragma unroll
    for (int i = 0; i < 8; i++)
        if (i < nv)
            cpasync16(wbuf_u + (uint32_t)(tid + i * 256) * 16, src + tid + i * 256);
    if (tid < 32)
        cpasync16(bias_u + (uint32_t)bslot * 512 + tid * 16,
                  reinterpret_cast<const float4*>(g_bimg + img * 128) + tid);
    asm volatile("cp.async.commit_group;" ::: "memory");
}

__global__ void __launch_bounds__(THREADS, 2)
critic_main(Params p) {
    extern __shared__ char smem[];
    const uint32_t sbase  = s2u(smem);
    const uint32_t wbuf_u = sbase + WBUF_OFF;
    const uint32_t bias_u = sbase + BIAS_OFF;
    float* biasf = reinterpret_cast<float*>(smem + BIAS_OFF);

    const int tid  = threadIdx.x;
    const int lane = tid & 31;
    const int wid  = tid >> 5;
    const int wm   = wid & 1;           // 2 warps over m (32 rows each)
    const int wn   = wid >> 1;          // 4 warps over n (32 each)
    const int mbase = wm * 32;
    const int nbase = wn * 32;
    const int lq = lane >> 2, lr = lane & 3;
    const int r8 = lane & 7, sel = lane >> 3;
    const int row0 = blockIdx.x * BM;
    const bool lowN = (wn < 2);

    const int rA0 = mbase + (sel & 1) * 8 + r8;
    const int rB0 = nbase + (sel >> 1) * 8 + r8;
    const uint32_t eA4 = (uint32_t)(((sel >> 1) ^ r8) << 4);
    const uint32_t eB4 = (uint32_t)(((sel & 1) ^ r8) << 4);
    const uint32_t aoff0 = (uint32_t)rA0 * 256;
    const uint32_t aoff1 = aoff0 + 16 * 256;
    const uint32_t bb0 = wbuf_u + (uint32_t)rB0 * 256;
    const uint32_t bb1 = bb0 + 16 * 256;

    const float m = __ldg(p.mixf);
    const float inv_m = 1.0f - m;
    float Pk[4];
    #pragma unroll
    for (int k = 0; k < 4; k++) Pk[k] = __ldg(p.P + k);

    prefetch_img(wbuf_u, bias_u, 0, 0, tid);    // prime stream 0

    for (int h = 0; h < 2; h++) {
        // ---- xu -> act buffer 4 (fp16, swizzled) ----
        {
            char* dst = smem + 4 * ACT_B;
            #pragma unroll
            for (int i = tid; i < BM * 16; i += THREADS) {
                const int r = i >> 4, ch = i & 15;
                float4 v0, v1;
                if (ch < 12) {
                    const float* src = p.x + (size_t)(row0 + r) * 96 + ch * 8;
                    v0 = *reinterpret_cast<const float4*>(src);
                    v1 = *reinterpret_cast<const float4*>(src + 4);
                } else {
                    const float* src = p.u + (size_t)(row0 + r) * 32 + (ch - 12) * 8;
                    v0 = *reinterpret_cast<const float4*>(src);
                    v1 = *reinterpret_cast<const float4*>(src + 4);
                }
                __half2 t0 = __floats2half2_rn(v0.x, v0.y);
                __half2 t1 = __floats2half2_rn(v0.z, v0.w);
                __half2 t2 = __floats2half2_rn(v1.x, v1.y);
                __half2 t3 = __floats2half2_rn(v1.z, v1.w);
                uint4 o;
                o.x = *reinterpret_cast<uint32_t*>(&t0);
                o.y = *reinterpret_cast<uint32_t*>(&t1);
                o.z = *reinterpret_cast<uint32_t*>(&t2);
                o.w = *reinterpret_cast<uint32_t*>(&t3);
                *reinterpret_cast<uint4*>(dst + r * 256 + ((ch ^ (r & 7)) << 4)) = o;
            }
        }

        float mix[2][4][4];
        for (int t = 0; t < 15; t++) {
            const int g = h * 15 + t;
            const int L = t / 5, s = t % 5;
            const bool is_main = (s == 4);
            const bool active  = (L < 2) || lowN;
            if (s == 0) {
                #pragma unroll
                for (int mt = 0; mt < 2; mt++)
                    #pragma unroll
                    for (int nt = 0; nt < 4; nt++)
                        #pragma unroll
                        for (int c = 0; c < 4; c++) mix[mt][nt][c] = 0.f;
            }

            asm volatile("cp.async.wait_group 0;" ::: "memory");
            __syncthreads();

            float acc[2][4][4];
            #pragma unroll
            for (int mt = 0; mt < 2; mt++)
                #pragma unroll
                for (int nt = 0; nt < 4; nt++)
                    #pragma unroll
                    for (int c = 0; c < 4; c++) acc[mt][nt][c] = 0.f;

            if (active) {
                const int inb = (L == 0) ? 4 : (is_main ? 4 : s);
                const uint32_t ab0 = sbase + (uint32_t)inb * ACT_B + aoff0;
                const uint32_t ab1 = sbase + (uint32_t)inb * ACT_B + aoff1;

                #pragma unroll
                for (int j = 0; j < 8; j++) {
                    const uint32_t tA = ((uint32_t)(j << 5)) ^ eA4;
                    const uint32_t tB = ((uint32_t)(j << 5)) ^ eB4;
                    uint32_t fa0[4], fa1[4], fb0[4], fb1[4];
                    ldsm4(fa0, ab0 + tA);
                    ldsm4(fa1, ab1 + tA);
                    ldsm4(fb0, bb0 + tB);
                    ldsm4(fb1, bb1 + tB);
                    mma16(acc[0][0], fa0, fb0[0], fb0[1]);
                    mma16(acc[0][1], fa0, fb0[2], fb0[3]);
                    mma16(acc[0][2], fa0, fb1[0], fb1[1]);
                    mma16(acc[0][3], fa0, fb1[2], fb1[3]);
                    mma16(acc[1][0], fa1, fb0[0], fb0[1]);
                    mma16(acc[1][1], fa1, fb0[2], fb0[3]);
                    mma16(acc[1][2], fa1, fb1[0], fb1[1]);
                    mma16(acc[1][3], fa1, fb1[2], fb1[3]);
                }
            }

            __syncthreads();    // wbuf + act reads done

            // single-buffer pipeline: fetch next stream's weights now;
            // bias double-buffered (this stream reads slot g&1).
            prefetch_img(wbuf_u, bias_u, (g + 1) % 30, (g + 1) & 1, tid);

            if (active) {
                const float sc = is_main ? inv_m : (m * Pk[s]);
                const float* bs = biasf + (g & 1) * 128;
                float bias[4][2];
                #pragma unroll
                for (int nt = 0; nt < 4; nt++) {
                    bias[nt][0] = bs[nbase + nt * 8 + lr * 2 + 0];
                    bias[nt][1] = bs[nbase + nt * 8 + lr * 2 + 1];
                }
                const bool do_store = is_main || (L < 2);
                char* outb = smem + (is_main ? 4 : s) * ACT_B;
                #pragma unroll
                for (int mt = 0; mt < 2; mt++)
                    #pragma unroll
                    for (int nt = 0; nt < 4; nt++)
                        #pragma unroll
                        for (int c2 = 0; c2 < 2; c2++) {
                            const float v0 = acc[mt][nt][c2 * 2 + 0] + bias[nt][0];
                            const float v1 = acc[mt][nt][c2 * 2 + 1] + bias[nt][1];
                            float o0, o1;
                            if (!is_main) {
                                mix[mt][nt][c2 * 2 + 0] = fmaf(sc, v0, mix[mt][nt][c2 * 2 + 0]);
                                mix[mt][nt][c2 * 2 + 1] = fmaf(sc, v1, mix[mt][nt][c2 * 2 + 1]);
                                o0 = v0; o1 = v1;
                            } else {
                                o0 = fmaf(sc, v0, mix[mt][nt][c2 * 2 + 0]);
                                o1 = fmaf(sc, v1, mix[mt][nt][c2 * 2 + 1]);
                            }
                            if (do_store) {
                                const int row = mbase + mt * 16 + lq + c2 * 8;
                                __half2 hv = __floats2half2_rn(fmaxf(o0, 0.f),
                                                               fmaxf(o1, 0.f));
                                *reinterpret_cast<uint32_t*>(
                                    outb + row * 256 +
                                    ((((nbase >> 3) + nt) ^ (row & 7)) << 4) +
                                    lr * 4) = *reinterpret_cast<uint32_t*>(&hv);
                            }
                        }
            }
        }

        __syncthreads();
        // ---- final layer: out = h3 . W4 + b4 ----
        if (tid < BM) {
            float sum = __ldg(p.b4[h]);
            const float* W4 = p.W4[h];
            const char* hb = smem + 4 * ACT_B;
            #pragma unroll
            for (int k2 = 0; k2 < 64; k2++) {
                const __half hv = *reinterpret_cast<const __half*>(
                    hb + tid * 256 + (((k2 >> 3) ^ (tid & 7)) << 4) + (k2 & 7) * 2);
                sum = fmaf(__half2float(hv), __ldg(W4 + k2), sum);
            }
            p.out[(size_t)h * BATCH + row0 + tid] = sum;
        }
        __syncthreads();   // buf4 free before next head's xu reload
    }
}

extern "C" void kernel_launch(void* const* d_in, const int* in_sizes, int n_in,
                              void* d_out, int out_size) {
    (void)in_sizes; (void)n_in; (void)out_size;
    Params p;
    p.x    = (const float*)d_in[0];
    p.u    = (const float*)d_in[1];
    p.mixf = (const float*)d_in[2];
    p.P    = (const float*)d_in[3];
    for (int h = 0; h < 2; h++) {
        const int base = 4 + h * 8;
        p.W[h][0]  = (const float*)d_in[base + 0];
        p.Bb[h][0] = (const float*)d_in[base + 1];
        p.W[h][1]  = (const float*)d_in[base + 2];
        p.Bb[h][1] = (const float*)d_in[base + 3];
        p.W[h][2]  = (const float*)d_in[base + 4];
        p.Bb[h][2] = (const float*)d_in[base + 5];
        p.W4[h]    = (const float*)d_in[base + 6];
        p.b4[h]    = (const float*)d_in[base + 7];
        const int tbase = 20 + h * 6;
        p.tW[h][0] = (const float*)d_in[tbase + 0];
        p.tb[h][0] = (const float*)d_in[tbase + 1];
        p.tW[h][1] = (const float*)d_in[tbase + 2];
        p.tb[h][1] = (const float*)d_in[tbase + 3];
        p.tW[h][2] = (const float*)d_in[tbase + 4];
        p.tb[h][2] = (const float*)d_in[tbase + 5];
    }
    p.out = (float*)d_out;

    prep_kernel<<<(30 * 2048 + 960 + 255) / 256, 256>>>(p);
    cudaFuncSetAttribute(critic_main,
                         cudaFuncAttributeMaxDynamicSharedMemorySize, SMEM_BYTES);
    critic_main<<<NBLK, THREADS, SMEM_BYTES>>>(p);
}